// round 3
// baseline (speedup 1.0000x reference)
#include <cuda_runtime.h>
#include <cstdint>
#include <math.h>

#define GO_TAG 1
#define NEGV   -10000.0f
#define K_     64
#define MAXELEMS_ (1024u * 512u * 64u)

// Scratch: alpha history rows 1..len-1 per batch, trans tables.
__device__ float g_trans[K_ * K_];    // trans[i][j] = score(i -> j)
__device__ float g_transT[K_ * K_];   // transT[j][i] = trans[i][j]
__device__ float g_alpha[MAXELEMS_];

// ---------------------------------------------------------------------------
// Kernel 1: detect which of (c0, c1) is the int {0,1} mask, then
// trans = log_softmax(A + mask * NEG, axis=-1), plus transpose.
// Double-precision internals: correctly rounded, ~1 ULP of f32 reference.
// ---------------------------------------------------------------------------
__global__ void trans_kernel(const float* __restrict__ c0,
                             const float* __restrict__ c1) {
    __shared__ int s_cnt;
    const int r = threadIdx.x;
    if (r == 0) s_cnt = 0;
    __syncthreads();

    // Row-vote: is c0 an int mask (all bit patterns 0 or 1)?
    bool ok = true;
    #pragma unroll
    for (int c = 0; c < K_; c++) {
        unsigned u = ((const unsigned*)c0)[r * K_ + c];
        ok &= (u <= 1u);
    }
    if (ok) atomicAdd(&s_cnt, 1);
    __syncthreads();
    const bool c0_is_mask = (s_cnt == K_);
    const int*   mask = (const int*)(c0_is_mask ? c0 : c1);
    const float* A    = c0_is_mask ? c1 : c0;

    float x[K_];
    float m = -__int_as_float(0x7f800000);  // -inf
    #pragma unroll
    for (int c = 0; c < K_; c++) {
        float v = A[r * K_ + c] + (mask[r * K_ + c] ? NEGV : 0.0f);
        x[c] = v;
        m = fmaxf(m, v);
    }
    double s = 0.0;
    #pragma unroll
    for (int c = 0; c < K_; c++) {
        s += exp((double)(x[c] - m));
    }
    float l = (float)log(s);
    #pragma unroll
    for (int c = 0; c < K_; c++) {
        float v = (x[c] - m) - l;
        g_trans[r * K_ + c]  = v;
        g_transT[c * K_ + r] = v;
    }
}

// ---------------------------------------------------------------------------
// Kernel 2: fused forward Viterbi (max only, alpha history to gmem) +
// in-block backward (backpointer recomputed along the taken path only).
// grid = B blocks, 64 threads (thread j owns tag j). T is runtime.
// Output tags written as FLOAT32 (harness __output__ dtype).
// ---------------------------------------------------------------------------
__global__ void __launch_bounds__(64)
viterbi_kernel(const float* __restrict__ unary,
               const int* __restrict__ lengths,
               float* __restrict__ out,
               int T) {
    __shared__ float s_transT[K_ * K_];
    __shared__ __align__(16) float s_alpha[2][K_];
    __shared__ int s_last;

    const int b = blockIdx.x;
    const int j = threadIdx.x;

    // Transition column j into registers (fully unrolled -> fixed regs).
    float tr[K_];
    #pragma unroll
    for (int i = 0; i < K_; i++) tr[i] = g_trans[i * K_ + j];
    // Transposed table to shared (backward path).
    #pragma unroll
    for (int q = 0; q < K_; q++) s_transT[q * K_ + j] = g_transT[q * K_ + j];

    int len = lengths[b];                       // steps t = 1..len are live
    len = len < 1 ? 1 : (len > T ? T : len);    // defensive clamp
    float alpha = (j == GO_TAG) ? 0.0f : NEGV;  // GO frame
    s_alpha[0][j] = alpha;

    const size_t bstride = (size_t)T * K_;
    float* arow = g_alpha + (size_t)b * bstride;
    const float* up = unary + (size_t)b * bstride + j;

    // Prefetch unary, depth 2.
    float u0 = up[0];
    float u1 = (len > 1) ? up[K_] : 0.0f;
    __syncthreads();

    // -------------------- forward --------------------
    for (int t = 1; t <= len; t++) {
        const float4* av = (const float4*)s_alpha[(t - 1) & 1];
        float4 v = av[0];
        float m0 = v.x + tr[0];
        float m1 = v.y + tr[1];
        float m2 = v.z + tr[2];
        float m3 = v.w + tr[3];
        #pragma unroll
        for (int q = 1; q < 16; q++) {
            v = av[q];
            m0 = fmaxf(m0, v.x + tr[4 * q + 0]);
            m1 = fmaxf(m1, v.y + tr[4 * q + 1]);
            m2 = fmaxf(m2, v.z + tr[4 * q + 2]);
            m3 = fmaxf(m3, v.w + tr[4 * q + 3]);
        }
        float best = fmaxf(fmaxf(m0, m1), fmaxf(m2, m3));
        alpha = best + u0;
        u0 = u1;
        if (t + 2 <= len) u1 = up[(size_t)(t + 1) * K_];
        s_alpha[t & 1][j] = alpha;
        if (t < len) arow[(size_t)t * K_ + j] = alpha;  // rows 1..len-1
        __syncthreads();
    }

    // last = argmax_j(final alpha), first-index tiebreak (exact scan).
    if (j == 0) {
        const float* af = s_alpha[len & 1];
        float bv = af[0];
        int bi = 0;
        #pragma unroll
        for (int i = 1; i < K_; i++) {
            if (af[i] > bv) { bv = af[i]; bi = i; }
        }
        s_last = bi;
    }
    __syncthreads();
    const int last = s_last;

    // Output positions tau >= len-1 all equal `last`.
    float* ob = out + (size_t)b * T;
    const float lastf = (float)last;
    for (int tau = (len - 1) + j; tau < T; tau += K_) ob[tau] = lastf;

    // -------------------- backward (warp 0) --------------------
    if (j < 32) {
        const int lane = j;
        int tag = last;

        // Alpha row prefetch pipeline, depth 2 (addresses independent of tag).
        float2 a = make_float2(0.f, 0.f), p = make_float2(0.f, 0.f);
        if (len >= 2) a = ((const float2*)(arow + (size_t)(len - 1) * K_))[lane];
        if (len >= 3) p = ((const float2*)(arow + (size_t)(len - 2) * K_))[lane];

        for (int t = len; t >= 2; t--) {
            // candidates i = 2*lane, 2*lane+1 over alpha_{t-1} + trans[:, tag]
            float2 tt = ((const float2*)(s_transT + tag * K_))[lane];
            float c0 = a.x + tt.x;
            float c1 = a.y + tt.y;
            float v;
            int li;
            if (c0 >= c1) { v = c0; li = 2 * lane; }      // lower index on tie
            else          { v = c1; li = 2 * lane + 1; }
            // Order-preserving uint key (no NaNs here).
            unsigned bits = __float_as_uint(v);
            unsigned key = ((int)bits < 0) ? ~bits : (bits | 0x80000000u);
            unsigned mx = __reduce_max_sync(0xffffffffu, key);
            // First-index tiebreak: maximize (63 - li) among winners.
            unsigned sel = (key == mx) ? (unsigned)(K_ - 1 - li) : 0u;
            unsigned w = __reduce_max_sync(0xffffffffu, sel);
            tag = (K_ - 1) - (int)w;
            if (lane == 0) ob[t - 2] = (float)tag;

            a = p;
            if (t >= 3) {
                // row (t-3) feeds iteration t-2 (valid: t-3 >= 0)
                p = ((const float2*)(arow + (size_t)(t - 3) * K_))[lane];
            }
        }
    }
}

extern "C" void kernel_launch(void* const* d_in, const int* in_sizes, int n_in,
                              void* d_out, int out_size) {
    // ----- identify inputs by SIZE, not position -----
    // unary: unique largest. The two equal-sized K*K arrays: {inv_mask, A}
    // (disambiguated on-device). Leftover: lengths (size B).
    int iu = 0;
    for (int i = 1; i < n_in; i++)
        if (in_sizes[i] > in_sizes[iu]) iu = i;

    int pair[2] = {-1, -1};
    int ilen = -1;
    for (int i = 0; i < n_in; i++) {
        if (i == iu) continue;
        for (int k = 0; k < n_in; k++) {
            if (k == i || k == iu) continue;
            if (in_sizes[k] == in_sizes[i]) { pair[0] = i < k ? i : k; pair[1] = i < k ? k : i; }
        }
    }
    for (int i = 0; i < n_in; i++)
        if (i != iu && i != pair[0] && i != pair[1]) ilen = i;
    if (ilen < 0) {  // degenerate fallback: assume dict order
        iu = 0; ilen = 1; pair[0] = 2; pair[1] = 3;
    }

    const float* unary   = (const float*)d_in[iu];
    const int*   lengths = (const int*)d_in[ilen];
    const float* c0      = (const float*)d_in[pair[0]];
    const float* c1      = (const float*)d_in[pair[1]];
    float* out = (float*)d_out;

    const int B = in_sizes[ilen];
    const int T = (int)((long long)in_sizes[iu] / ((long long)B * K_));

    trans_kernel<<<1, 64>>>(c0, c1);
    viterbi_kernel<<<B, 64>>>(unary, lengths, out, T);
}

// round 4
// speedup vs baseline: 1.8770x; 1.8770x over previous
#include <cuda_runtime.h>
#include <cstdint>
#include <math.h>

#define GO_TAG 1
#define NEGV   -10000.0f
#define K_     64
#define MAXELEMS_ (1024u * 512u * 64u)

// Scratch: alpha history rows 1..len-1 per batch, trans tables.
__device__ float g_trans[K_ * K_];    // trans[i][j] = score(i -> j)
__device__ float g_transT[K_ * K_];   // transT[j][i] = trans[i][j]
__device__ float g_alpha[MAXELEMS_];

__device__ __forceinline__ void cp_async16(uint32_t saddr, const void* gptr) {
    asm volatile("cp.async.ca.shared.global [%0], [%1], 16;"
                 :: "r"(saddr), "l"(gptr));
}
__device__ __forceinline__ void cp_commit() {
    asm volatile("cp.async.commit_group;");
}
template <int N>
__device__ __forceinline__ void cp_wait() {
    asm volatile("cp.async.wait_group %0;" :: "n"(N));
}

// ---------------------------------------------------------------------------
// Kernel 1: detect which of (c0, c1) is the int {0,1} mask, then
// trans = log_softmax(A + mask * NEG, axis=-1), plus transpose.
// Double-precision internals: correctly rounded, ~1 ULP of f32 reference.
// ---------------------------------------------------------------------------
__global__ void trans_kernel(const float* __restrict__ c0,
                             const float* __restrict__ c1) {
    __shared__ int s_cnt;
    const int r = threadIdx.x;
    if (r == 0) s_cnt = 0;
    __syncthreads();

    bool ok = true;
    #pragma unroll
    for (int c = 0; c < K_; c++) {
        unsigned u = ((const unsigned*)c0)[r * K_ + c];
        ok &= (u <= 1u);
    }
    if (ok) atomicAdd(&s_cnt, 1);
    __syncthreads();
    const bool c0_is_mask = (s_cnt == K_);
    const int*   mask = (const int*)(c0_is_mask ? c0 : c1);
    const float* A    = c0_is_mask ? c1 : c0;

    float x[K_];
    float m = -__int_as_float(0x7f800000);
    #pragma unroll
    for (int c = 0; c < K_; c++) {
        float v = A[r * K_ + c] + (mask[r * K_ + c] ? NEGV : 0.0f);
        x[c] = v;
        m = fmaxf(m, v);
    }
    double s = 0.0;
    #pragma unroll
    for (int c = 0; c < K_; c++) s += exp((double)(x[c] - m));
    float l = (float)log(s);
    #pragma unroll
    for (int c = 0; c < K_; c++) {
        float v = (x[c] - m) - l;
        g_trans[r * K_ + c]  = v;
        g_transT[c * K_ + r] = v;
    }
}

// ---------------------------------------------------------------------------
// Kernel 2: fused forward Viterbi (max only, alpha history to gmem) +
// in-block backward (backpointer recomputed along the taken path only).
// grid = B blocks, 64 threads (thread j owns tag j).
// Global-latency hiding: 8-step cp.async double-buffered staging for both
// the forward unary stream and the backward alpha-history stream.
// ---------------------------------------------------------------------------
__global__ void __launch_bounds__(64)
viterbi_kernel(const float* __restrict__ unary,
               const int* __restrict__ lengths,
               float* __restrict__ out,
               int T) {
    __shared__ float s_transT[K_ * K_];
    __shared__ __align__(16) float s_alpha[2][K_];
    __shared__ __align__(16) float s_u[2][8][K_];   // fwd unary / bwd alpha stage
    __shared__ int s_last;

    const int b = blockIdx.x;
    const int j = threadIdx.x;

    int len = lengths[b];
    len = len < 1 ? 1 : (len > T ? T : len);

    const size_t bstride = (size_t)T * K_;
    const float* ub = unary + (size_t)b * bstride;
    float* arow = g_alpha + (size_t)b * bstride;

    const uint32_t su_base = (uint32_t)__cvta_generic_to_shared(&s_u[0][0][0]);

    // ---- prefetch first unary chunk (steps 1..8 -> rows 0..7, clamped) ----
    {
        #pragma unroll
        for (int r = 0; r < 2; r++) {
            int l = j + r * 64;               // 0..127: 128 x 16B = 2KB
            int s = l >> 4;
            int c = (l & 15) * 4;
            int row = s; if (row > T - 1) row = T - 1;
            cp_async16(su_base + (uint32_t)(s * K_ + c) * 4,
                       ub + (size_t)row * K_ + c);
        }
        cp_commit();
    }

    // Transition column j into registers.
    float tr[K_];
    #pragma unroll
    for (int i = 0; i < K_; i++) tr[i] = g_trans[i * K_ + j];
    // Transposed table to shared (backward path).
    #pragma unroll
    for (int q = 0; q < K_; q++) s_transT[q * K_ + j] = g_transT[q * K_ + j];

    float alpha = (j == GO_TAG) ? 0.0f : NEGV;
    s_alpha[0][j] = alpha;
    __syncthreads();

    // -------------------- forward --------------------
    int cbuf = 0;
    for (int t0 = 1; t0 <= len; t0 += 8) {
        // Prefetch next chunk into cbuf^1 (uniform condition).
        if (t0 + 8 <= len) {
            #pragma unroll
            for (int r = 0; r < 2; r++) {
                int l = j + r * 64;
                int s = l >> 4;
                int c = (l & 15) * 4;
                int row = t0 + 7 + s;          // rows (t0+8-1)+s
                if (row > T - 1) row = T - 1;
                cp_async16(su_base + (uint32_t)(((cbuf ^ 1) * 8 + s) * K_ + c) * 4,
                           ub + (size_t)row * K_ + c);
            }
        }
        cp_commit();     // always commit (possibly empty group)
        cp_wait<1>();    // current chunk (older group) now complete
        __syncthreads(); // cp.async data visible to both warps

        const int tend = (t0 + 7 < len) ? t0 + 7 : len;
        #pragma unroll
        for (int s = 0; s < 8; s++) {
            const int t = t0 + s;
            if (t <= tend) {                  // uniform per block
                const float u = s_u[cbuf][s][j];
                const float4* av = (const float4*)s_alpha[(t - 1) & 1];
                float4 v = av[0];
                float m0 = v.x + tr[0];
                float m1 = v.y + tr[1];
                float m2 = v.z + tr[2];
                float m3 = v.w + tr[3];
                #pragma unroll
                for (int q = 1; q < 16; q++) {
                    v = av[q];
                    m0 = fmaxf(m0, v.x + tr[4 * q + 0]);
                    m1 = fmaxf(m1, v.y + tr[4 * q + 1]);
                    m2 = fmaxf(m2, v.z + tr[4 * q + 2]);
                    m3 = fmaxf(m3, v.w + tr[4 * q + 3]);
                }
                alpha = fmaxf(fmaxf(m0, m1), fmaxf(m2, m3)) + u;
                s_alpha[t & 1][j] = alpha;
                if (t < len) arow[(size_t)t * K_ + j] = alpha;  // rows 1..len-1
                __syncthreads();
            }
        }
        cbuf ^= 1;
    }

    // last = argmax_j(final alpha), first-index tiebreak (exact scan).
    if (j == 0) {
        const float* af = s_alpha[len & 1];
        float bv = af[0];
        int bi = 0;
        #pragma unroll
        for (int i = 1; i < K_; i++) {
            if (af[i] > bv) { bv = af[i]; bi = i; }
        }
        s_last = bi;
    }
    __syncthreads();
    const int last = s_last;

    // Output positions tau >= len-1 all equal `last`.
    float* ob = out + (size_t)b * T;
    const float lastf = (float)last;
    for (int tau = (len - 1) + j; tau < T; tau += K_) ob[tau] = lastf;

    // -------------------- backward (warp 0) --------------------
    // Reuses s_u as the alpha-history stage (warp 1 is done with it).
    if (j < 32 && len >= 2) {
        const int lane = j;
        int tag = last;

        // Prefetch first chunk: rows (len-1-s), s=0..7, clamped >= 0.
        #pragma unroll
        for (int r = 0; r < 4; r++) {
            int l = lane + r * 32;
            int s = l >> 4;
            int c = (l & 15) * 4;
            int row = len - 1 - s; if (row < 0) row = 0;
            cp_async16(su_base + (uint32_t)(s * K_ + c) * 4,
                       arow + (size_t)row * K_ + c);
        }
        cp_commit();

        int bbuf = 0;
        for (int tb = len; tb >= 2; tb -= 8) {
            if (tb - 8 >= 2) {
                #pragma unroll
                for (int r = 0; r < 4; r++) {
                    int l = lane + r * 32;
                    int s = l >> 4;
                    int c = (l & 15) * 4;
                    int row = tb - 9 - s; if (row < 0) row = 0;
                    cp_async16(su_base + (uint32_t)(((bbuf ^ 1) * 8 + s) * K_ + c) * 4,
                               arow + (size_t)row * K_ + c);
                }
            }
            cp_commit();
            cp_wait<1>();
            __syncwarp();

            const int tlo = (tb - 7 > 2) ? tb - 7 : 2;
            #pragma unroll
            for (int s = 0; s < 8; s++) {
                const int t = tb - s;
                if (t >= tlo) {               // uniform across warp
                    float2 a = ((const float2*)&s_u[bbuf][s][0])[lane];
                    float2 tt = ((const float2*)(s_transT + tag * K_))[lane];
                    float c0 = a.x + tt.x;
                    float c1 = a.y + tt.y;
                    float v; int li;
                    if (c0 >= c1) { v = c0; li = 2 * lane; }
                    else          { v = c1; li = 2 * lane + 1; }
                    unsigned bits = __float_as_uint(v);
                    unsigned key = ((int)bits < 0) ? ~bits : (bits | 0x80000000u);
                    unsigned mx = __reduce_max_sync(0xffffffffu, key);
                    unsigned sel = (key == mx) ? (unsigned)(K_ - 1 - li) : 0u;
                    unsigned w = __reduce_max_sync(0xffffffffu, sel);
                    tag = (K_ - 1) - (int)w;
                    if (lane == 0) ob[t - 2] = (float)tag;
                }
            }
            bbuf ^= 1;
        }
    }
}

extern "C" void kernel_launch(void* const* d_in, const int* in_sizes, int n_in,
                              void* d_out, int out_size) {
    // ----- identify inputs by SIZE, not position -----
    int iu = 0;
    for (int i = 1; i < n_in; i++)
        if (in_sizes[i] > in_sizes[iu]) iu = i;

    int pair[2] = {-1, -1};
    int ilen = -1;
    for (int i = 0; i < n_in; i++) {
        if (i == iu) continue;
        for (int k = 0; k < n_in; k++) {
            if (k == i || k == iu) continue;
            if (in_sizes[k] == in_sizes[i]) { pair[0] = i < k ? i : k; pair[1] = i < k ? k : i; }
        }
    }
    for (int i = 0; i < n_in; i++)
        if (i != iu && i != pair[0] && i != pair[1]) ilen = i;
    if (ilen < 0) { iu = 0; ilen = 1; pair[0] = 2; pair[1] = 3; }

    const float* unary   = (const float*)d_in[iu];
    const int*   lengths = (const int*)d_in[ilen];
    const float* c0      = (const float*)d_in[pair[0]];
    const float* c1      = (const float*)d_in[pair[1]];
    float* out = (float*)d_out;

    const int B = in_sizes[ilen];
    const int T = (int)((long long)in_sizes[iu] / ((long long)B * K_));

    trans_kernel<<<1, 64>>>(c0, c1);
    viterbi_kernel<<<B, 64>>>(unary, lengths, out, T);
}

// round 5
// speedup vs baseline: 2.4079x; 1.2829x over previous
#include <cuda_runtime.h>
#include <cstdint>
#include <math.h>

#define GO_TAG 1
#define NEGV   -10000.0f
#define K_     64
#define MAXELEMS_ (1024u * 512u * 64u)

// Scratch: alpha history rows 1..len-1 per batch, trans tables.
__device__ float g_trans[K_ * K_];    // trans[i][j] = score(i -> j)
__device__ float g_transT[K_ * K_];   // transT[j][i] = trans[i][j]
__device__ float g_alpha[MAXELEMS_];

__device__ __forceinline__ void cp_async16(uint32_t saddr, const void* gptr) {
    asm volatile("cp.async.ca.shared.global [%0], [%1], 16;"
                 :: "r"(saddr), "l"(gptr));
}
__device__ __forceinline__ void cp_commit() {
    asm volatile("cp.async.commit_group;");
}
template <int N>
__device__ __forceinline__ void cp_wait() {
    asm volatile("cp.async.wait_group %0;" :: "n"(N));
}

// ---------------------------------------------------------------------------
// Kernel 1: trans = log_softmax(A + mask * NEG, axis=-1) + transpose.
// 64 blocks (one per row) x 64 threads (one per col). Double internals:
// exp/log in double, sum tree-reduced in double (29 extra bits vs f32 =>
// rounding to f32 is order-invariant in practice; R3/R4 measured rel_err 0.0).
// ---------------------------------------------------------------------------
__global__ void __launch_bounds__(64)
trans_kernel(const float* __restrict__ c0, const float* __restrict__ c1) {
    __shared__ float  s_m[2];
    __shared__ double s_s[2];
    const int r = blockIdx.x;
    const int c = threadIdx.x;
    const int w = c >> 5;
    const int lane = c & 31;

    // Row-vote: is c0 the int {0,1} mask? (my row all bit patterns <= 1)
    unsigned u0 = ((const unsigned*)c0)[r * K_ + c];
    const bool c0_is_mask = __syncthreads_and(u0 <= 1u);
    const int*   mask = (const int*)(c0_is_mask ? c0 : c1);
    const float* A    = c0_is_mask ? c1 : c0;

    float x = A[r * K_ + c] + (mask[r * K_ + c] ? NEGV : 0.0f);

    // Row max.
    float m = x;
    #pragma unroll
    for (int d = 16; d > 0; d >>= 1) m = fmaxf(m, __shfl_xor_sync(~0u, m, d));
    if (lane == 0) s_m[w] = m;
    __syncthreads();
    m = fmaxf(s_m[0], s_m[1]);

    // Row sum of exp in double.
    double e = exp((double)(x - m));
    #pragma unroll
    for (int d = 16; d > 0; d >>= 1) e += __shfl_xor_sync(~0u, e, d);
    if (lane == 0) s_s[w] = e;
    __syncthreads();
    const float l = (float)log(s_s[0] + s_s[1]);

    const float v = (x - m) - l;
    g_trans[r * K_ + c]  = v;
    g_transT[c * K_ + r] = v;
}

// ---------------------------------------------------------------------------
// Kernel 2: fused forward Viterbi + path-only backward.
// 128 threads = 2 independent groups of 64 (one sequence each), so the block
// occupies all 4 SMSPs (wid%4). Groups sync via named barriers (id 1+g) so a
// short sequence never waits on its partner. cp.async double-buffered staging
// (8 steps deep) for the forward unary stream and backward alpha stream.
// ---------------------------------------------------------------------------
__global__ void __launch_bounds__(128)
viterbi_kernel(const float* __restrict__ unary,
               const int* __restrict__ lengths,
               float* __restrict__ out,
               int T, int B) {
    __shared__ __align__(16) float s_transT[K_ * K_];      // shared, read-only
    __shared__ __align__(16) float s_alpha[2][2][K_];       // [g][buf][j]
    __shared__ __align__(16) float s_u[2][2][8][K_];        // [g][buf][s][j]
    __shared__ int s_last[2];

    const int tid = threadIdx.x;
    const int g = tid >> 6;
    const int j = tid & 63;
    const int b = blockIdx.x * 2 + g;
    const int nbar = 1 + g;
    const bool live = (b < B);

    #define GBAR() asm volatile("bar.sync %0, 64;" :: "r"(nbar) : "memory")

    int len = 1;
    const float* ub = unary;
    float* arow = g_alpha;
    const uint32_t su_base =
        (uint32_t)__cvta_generic_to_shared(&s_u[g][0][0][0]);

    if (live) {
        len = lengths[b];
        len = len < 1 ? 1 : (len > T ? T : len);
        const size_t bstride = (size_t)T * K_;
        ub = unary + (size_t)b * bstride;
        arow = g_alpha + (size_t)b * bstride;

        // ---- prefetch first unary chunk (steps 1..8 -> rows 0..7) ----
        #pragma unroll
        for (int rr = 0; rr < 2; rr++) {
            int l = j + rr * 64;              // 0..127: 128 x 16B = 2KB
            int s = l >> 4;
            int c = (l & 15) * 4;
            int row = s; if (row > T - 1) row = T - 1;
            cp_async16(su_base + (uint32_t)(s * K_ + c) * 4,
                       ub + (size_t)row * K_ + c);
        }
        cp_commit();
    }

    // Shared transposed table (cooperative copy, all 128 threads).
    {
        const float4* src = (const float4*)g_transT;
        float4* dst = (float4*)s_transT;
        #pragma unroll
        for (int q = 0; q < 8; q++) dst[tid + q * 128] = src[tid + q * 128];
    }

    // Transition column j into registers.
    float tr[K_];
    #pragma unroll
    for (int i = 0; i < K_; i++) tr[i] = g_trans[i * K_ + j];

    float alpha = (j == GO_TAG) ? 0.0f : NEGV;
    s_alpha[g][0][j] = alpha;
    __syncthreads();      // transT + s_alpha visible block-wide
    if (!live) return;

    // -------------------- forward --------------------
    int cbuf = 0;
    for (int t0 = 1; t0 <= len; t0 += 8) {
        if (t0 + 8 <= len) {
            #pragma unroll
            for (int rr = 0; rr < 2; rr++) {
                int l = j + rr * 64;
                int s = l >> 4;
                int c = (l & 15) * 4;
                int row = t0 + 7 + s;
                if (row > T - 1) row = T - 1;
                cp_async16(su_base + (uint32_t)(((cbuf ^ 1) * 8 + s) * K_ + c) * 4,
                           ub + (size_t)row * K_ + c);
            }
        }
        cp_commit();      // always commit (possibly empty group)
        cp_wait<1>();     // current chunk complete
        GBAR();           // visible to both warps of this group

        const int tend = (t0 + 7 < len) ? t0 + 7 : len;
        #pragma unroll
        for (int s = 0; s < 8; s++) {
            const int t = t0 + s;
            if (t <= tend) {                 // uniform per group
                const float u = s_u[g][cbuf][s][j];
                const float4* av = (const float4*)s_alpha[g][(t - 1) & 1];
                float4 v = av[0];
                float m0 = v.x + tr[0];
                float m1 = v.y + tr[1];
                float m2 = v.z + tr[2];
                float m3 = v.w + tr[3];
                #pragma unroll
                for (int q = 1; q < 16; q++) {
                    v = av[q];
                    m0 = fmaxf(m0, v.x + tr[4 * q + 0]);
                    m1 = fmaxf(m1, v.y + tr[4 * q + 1]);
                    m2 = fmaxf(m2, v.z + tr[4 * q + 2]);
                    m3 = fmaxf(m3, v.w + tr[4 * q + 3]);
                }
                alpha = fmaxf(fmaxf(m0, m1), fmaxf(m2, m3)) + u;
                s_alpha[g][t & 1][j] = alpha;
                if (t < len) arow[(size_t)t * K_ + j] = alpha;  // rows 1..len-1
                GBAR();
            }
        }
        cbuf ^= 1;
    }

    // last = argmax_j(final alpha), first-index tiebreak (exact scan).
    if (j == 0) {
        const float* af = s_alpha[g][len & 1];
        float bv = af[0];
        int bi = 0;
        #pragma unroll
        for (int i = 1; i < K_; i++) {
            if (af[i] > bv) { bv = af[i]; bi = i; }
        }
        s_last[g] = bi;
    }
    GBAR();
    const int last = s_last[g];

    // Output positions tau >= len-1 all equal `last`.
    float* ob = out + (size_t)b * T;
    const float lastf = (float)last;
    for (int tau = (len - 1) + j; tau < T; tau += K_) ob[tau] = lastf;

    // -------------------- backward (warp 0 of group) --------------------
    if (j < 32 && len >= 2) {
        const int lane = j;
        int tag = last;

        // Prefetch first chunk: rows (len-1-s), s=0..7, clamped >= 0.
        #pragma unroll
        for (int rr = 0; rr < 4; rr++) {
            int l = lane + rr * 32;
            int s = l >> 4;
            int c = (l & 15) * 4;
            int row = len - 1 - s; if (row < 0) row = 0;
            cp_async16(su_base + (uint32_t)(s * K_ + c) * 4,
                       arow + (size_t)row * K_ + c);
        }
        cp_commit();

        int bbuf = 0;
        for (int tb = len; tb >= 2; tb -= 8) {
            if (tb - 8 >= 2) {
                #pragma unroll
                for (int rr = 0; rr < 4; rr++) {
                    int l = lane + rr * 32;
                    int s = l >> 4;
                    int c = (l & 15) * 4;
                    int row = tb - 9 - s; if (row < 0) row = 0;
                    cp_async16(su_base + (uint32_t)(((bbuf ^ 1) * 8 + s) * K_ + c) * 4,
                               arow + (size_t)row * K_ + c);
                }
            }
            cp_commit();
            cp_wait<1>();
            __syncwarp();

            const int tlo = (tb - 7 > 2) ? tb - 7 : 2;
            #pragma unroll
            for (int s = 0; s < 8; s++) {
                const int t = tb - s;
                if (t >= tlo) {              // uniform across warp
                    float2 a = ((const float2*)&s_u[g][bbuf][s][0])[lane];
                    float2 tt = ((const float2*)(s_transT + tag * K_))[lane];
                    float c0 = a.x + tt.x;
                    float c1 = a.y + tt.y;
                    float v; int li;
                    if (c0 >= c1) { v = c0; li = 2 * lane; }
                    else          { v = c1; li = 2 * lane + 1; }
                    unsigned bits = __float_as_uint(v);
                    unsigned key = ((int)bits < 0) ? ~bits : (bits | 0x80000000u);
                    unsigned mx = __reduce_max_sync(0xffffffffu, key);
                    unsigned sel = (key == mx) ? (unsigned)(K_ - 1 - li) : 0u;
                    unsigned w = __reduce_max_sync(0xffffffffu, sel);
                    tag = (K_ - 1) - (int)w;
                    if (lane == 0) ob[t - 2] = (float)tag;
                }
            }
            bbuf ^= 1;
        }
    }
    #undef GBAR
}

extern "C" void kernel_launch(void* const* d_in, const int* in_sizes, int n_in,
                              void* d_out, int out_size) {
    // ----- identify inputs by SIZE, not position -----
    int iu = 0;
    for (int i = 1; i < n_in; i++)
        if (in_sizes[i] > in_sizes[iu]) iu = i;

    int pair[2] = {-1, -1};
    int ilen = -1;
    for (int i = 0; i < n_in; i++) {
        if (i == iu) continue;
        for (int k = 0; k < n_in; k++) {
            if (k == i || k == iu) continue;
            if (in_sizes[k] == in_sizes[i]) { pair[0] = i < k ? i : k; pair[1] = i < k ? k : i; }
        }
    }
    for (int i = 0; i < n_in; i++)
        if (i != iu && i != pair[0] && i != pair[1]) ilen = i;
    if (ilen < 0) { iu = 0; ilen = 1; pair[0] = 2; pair[1] = 3; }

    const float* unary   = (const float*)d_in[iu];
    const int*   lengths = (const int*)d_in[ilen];
    const float* c0      = (const float*)d_in[pair[0]];
    const float* c1      = (const float*)d_in[pair[1]];
    float* out = (float*)d_out;

    const int B = in_sizes[ilen];
    const int T = (int)((long long)in_sizes[iu] / ((long long)B * K_));

    trans_kernel<<<K_, K_>>>(c0, c1);
    viterbi_kernel<<<(B + 1) / 2, 128>>>(unary, lengths, out, T, B);
}